// round 3
// baseline (speedup 1.0000x reference)
#include <cuda_runtime.h>

// Problem constants (fixed by the dataset)
#define NB    128          // graphs (B)
#define NN    256          // nodes per graph
#define DPE   16           // D_pe / eigen dim
#define MM    4            // M psi copies
#define HPSI  32
#define HP    16
#define HG    64
#define NSUM  (NB*NN)      // 32768
#define EDGES (NSUM*16)    // 524288
#define EPG   (EDGES/NB)   // 4096 edges per graph (graph-contiguous)
#define VPAD  20           // padded row stride (floats) -> conflict-free LDS.128

typedef unsigned long long u64;

// Scratch (device globals: no allocation allowed)
__device__ float g_x0[NSUM*HP];          // pooled features, o-half 0
__device__ float g_x1[NSUM*HP];          // pooled features, o-half 1
__device__ int   g_srt[EDGES];           // CSR: src sorted by dst (per graph)
__device__ int   g_start[NB*(NN+1)];     // CSR row starts (stride 257)

// ---------------- packed f32x2 helpers ----------------
__device__ __forceinline__ u64 pk2(float lo, float hi) {
    u64 r; asm("mov.b64 %0,{%1,%2};" : "=l"(r) : "f"(lo), "f"(hi)); return r;
}
__device__ __forceinline__ void upk2(u64 v, float& lo, float& hi) {
    asm("mov.b64 {%0,%1},%2;" : "=f"(lo), "=f"(hi) : "l"(v));
}
__device__ __forceinline__ u64 fma2(u64 a, u64 b, u64 c) {
    u64 d; asm("fma.rn.f32x2 %0,%1,%2,%3;" : "=l"(d) : "l"(a), "l"(b), "l"(c)); return d;
}
__device__ __forceinline__ u64 mul2(u64 a, u64 b) {
    u64 d; asm("mul.rn.f32x2 %0,%1,%2;" : "=l"(d) : "l"(a), "l"(b)); return d;
}
__device__ __forceinline__ u64 add2(u64 a, u64 b) {
    u64 d; asm("add.rn.f32x2 %0,%1,%2;" : "=l"(d) : "l"(a), "l"(b)); return d;
}

// ---------------------------------------------------------------------------
// K1: per-graph CSR build (histogram + warp-shuffle scan + scatter)
// ---------------------------------------------------------------------------
__global__ void __launch_bounds__(256) kernelCSR(const int* __restrict__ edge_index)
{
    __shared__ int cnt[NN];
    __shared__ int cur[NN];
    __shared__ int wsum[8];

    int b = blockIdx.x, t = threadIdx.x;
    int base = b*NN;
    cnt[t] = 0;
    __syncthreads();

    const int* srcp = edge_index + (size_t)b*EPG;
    const int* dstp = edge_index + (size_t)EDGES + (size_t)b*EPG;

    #pragma unroll
    for (int e = t; e < EPG; e += 256) atomicAdd(&cnt[dstp[e] - base], 1);
    __syncthreads();

    int v = cnt[t];
    int incl = v;
    #pragma unroll
    for (int off = 1; off < 32; off <<= 1) {
        int x = __shfl_up_sync(0xffffffffu, incl, off);
        if ((t & 31) >= off) incl += x;
    }
    if ((t & 31) == 31) wsum[t >> 5] = incl;
    __syncthreads();
    if (t == 0) {
        int s = 0;
        #pragma unroll
        for (int i = 0; i < 8; i++) { int x = wsum[i]; wsum[i] = s; s += x; }
    }
    __syncthreads();
    int excl = incl - v + wsum[t >> 5];
    g_start[b*(NN+1) + t] = excl;
    if (t == 0) g_start[b*(NN+1) + NN] = EPG;
    cur[t] = excl;
    __syncthreads();

    #pragma unroll
    for (int e = t; e < EPG; e += 256) {
        int d = dstp[e] - base;
        int pos = atomicAdd(&cur[d], 1);
        g_srt[(size_t)b*EPG + pos] = srcp[e] - base;
    }
}

// ---------------------------------------------------------------------------
// K2: fused psi + mask + pairwise phase, 2 CTAs per graph (o-range split).
//   CTA c=0: o = 0..64 ; CTA c=1: o = 65..128.
// ---------------------------------------------------------------------------
#define COMPUTE_R2(kk) do {                                                     \
    const ulonglong2* vr_ = (const ulonglong2*)&Vs[(kk)*VPAD];                  \
    u64 s_[4];                                                                  \
    {   ulonglong2 q0_ = vr_[0], q1_ = vr_[1];                                  \
        _Pragma("unroll")                                                       \
        for (int m_ = 0; m_ < 4; m_++) {                                        \
            u64 a_ = mul2(An2[m_][0], q0_.x);                                   \
            a_ = fma2(An2[m_][1], q0_.y, a_);                                   \
            a_ = fma2(An2[m_][2], q1_.x, a_);                                   \
            s_[m_] = fma2(An2[m_][3], q1_.y, a_);                               \
        }                                                                       \
    }                                                                           \
    {   ulonglong2 q2_ = vr_[2], q3_ = vr_[3];                                  \
        _Pragma("unroll")                                                       \
        for (int m_ = 0; m_ < 4; m_++) {                                        \
            u64 a_ = fma2(An2[m_][4], q2_.x, s_[m_]);                           \
            a_ = fma2(An2[m_][5], q2_.y, a_);                                   \
            a_ = fma2(An2[m_][6], q3_.x, a_);                                   \
            s_[m_] = fma2(An2[m_][7], q3_.y, a_);                               \
        }                                                                       \
    }                                                                           \
    u64 wm_[4];                                                                 \
    _Pragma("unroll")                                                           \
    for (int m_ = 0; m_ < 4; m_++) {                                            \
        float lo_, hi_; upk2(s_[m_], lo_, hi_);                                 \
        float w_ = lo_ + hi_;                                                   \
        wm_[m_] = pk2(w_, w_);                                                  \
    }                                                                           \
    _Pragma("unroll")                                                           \
    for (int hp_ = 0; hp_ < 8; hp_++) {                                         \
        u64 p_ = fma2(wm_[0], wpu[hp_], bpu[hp_]);                              \
        p_ = fma2(wm_[1], wpu[8+hp_], p_);                                      \
        p_ = fma2(wm_[2], wpu[16+hp_], p_);                                     \
        p_ = fma2(wm_[3], wpu[24+hp_], p_);                                     \
        float lo_, hi_; upk2(p_, lo_, hi_);                                     \
        lo_ = fmaxf(lo_, 0.f); hi_ = fmaxf(hi_, 0.f);                           \
        rp[hp_] = pk2(lo_, hi_);                                                \
    }                                                                           \
} while (0)

__global__ void __launch_bounds__(256, 2) kernelB(
        const float* __restrict__ V,
        const float* __restrict__ Lambda,
        const float* __restrict__ pW1, const float* __restrict__ pb1,
        const float* __restrict__ pW2, const float* __restrict__ pb2,
        const float* __restrict__ Wp1, const float* __restrict__ bp1,
        const int*   __restrict__ batch)
{
    extern __shared__ float sm[];
    float* Vs   = sm;                    // 5120 floats
    float* xch0 = sm + NN*VPAD;          // 5120
    float* xch1 = sm + 2*NN*VPAD;        // 5120
    float* zs   = sm + 3*NN*VPAD;        // 64
    float* wpS  = zs + 64;               // 64
    float* bpS  = wpS + 64;              // 16
    __shared__ int bnds[2];

    int b = blockIdx.x >> 1;
    int c = blockIdx.x & 1;
    int n = threadIdx.x;

    // Load V tile [256 x 16] into padded smem
    const float4* vg = (const float4*)(V + (size_t)b*NN*DPE);
    for (int i = n; i < NN*DPE/4; i += 256) {
        float4 v = vg[i];
        *(float4*)&Vs[(i >> 2)*VPAD + ((i & 3) << 2)] = v;
    }

    // psi MLP (threads 0..63), count via binary search (threads 254,255),
    // projection weights to smem (threads 64..143)
    float pacc = 0.f;
    if (n < DPE*MM) {
        int d = n >> 2, m = n & 3;
        float lam = Lambda[b*DPE + d];
        pacc = pb2[m];
        #pragma unroll
        for (int h = 0; h < HPSI; h++) {
            float v = fmaf(lam, pW1[m*HPSI + h], pb1[m*HPSI + h]);
            pacc = fmaf(fmaxf(v, 0.f), pW2[m*HPSI + h], pacc);
        }
    } else if (n < 128) {
        wpS[n - 64] = Wp1[n - 64];
    } else if (n < 144) {
        bpS[n - 128] = bp1[n - 128];
    } else if (n >= 254) {
        int key = b + (n - 254);        // first index with batch[i] >= key
        int lo = 0, hi = NSUM;
        while (lo < hi) {
            int mid = (lo + hi) >> 1;
            if (batch[mid] < key) lo = mid + 1; else hi = mid;
        }
        bnds[n - 254] = lo;
    }
    __syncthreads();
    if (n < DPE*MM) {
        int cnt = bnds[1] - bnds[0];
        zs[n] = ((n >> 2) < cnt) ? pacc : 0.f;
    }
    __syncthreads();

    const u64* wpu = (const u64*)wpS;
    const u64* bpu = (const u64*)bpS;

    // Per-thread packed scaled row: An2[m][j] = (V[n,2j]Z[2j,m], V[n,2j+1]Z[2j+1,m])
    u64 An2[MM][DPE/2];
    {
        const float4* vrow = (const float4*)&Vs[n*VPAD];
        #pragma unroll
        for (int q = 0; q < 4; q++) {
            float4 vv = vrow[q];
            #pragma unroll
            for (int m = 0; m < MM; m++) {
                An2[m][2*q]   = pk2(vv.x * zs[(4*q)*MM + m],   vv.y * zs[(4*q+1)*MM + m]);
                An2[m][2*q+1] = pk2(vv.z * zs[(4*q+2)*MM + m], vv.w * zs[(4*q+3)*MM + m]);
            }
        }
    }

    u64 acc2[HP/2];
    #pragma unroll
    for (int h = 0; h < HP/2; h++) acc2[h] = 0ull;

    u64 rp[8];

    // diagonal (o = 0), only in the c=0 CTA
    if (c == 0) {
        COMPUTE_R2(n);
        #pragma unroll
        for (int h = 0; h < 8; h++) acc2[h] = add2(acc2[h], rp[h]);
    }

    int o_lo = c ? 65 : 1;
    int o_hi = c ? 128 : 64;
    for (int o = o_lo; o <= o_hi; o++) {
        int  k   = (n + o) & 255;
        bool act = (o < 128) || (n < 128);   // o=128: only lower half computes
        float* xch = (o & 1) ? xch1 : xch0;
        if (act) {
            COMPUTE_R2(k);
            u64* xr = (u64*)&xch[n*VPAD];
            #pragma unroll
            for (int h = 0; h < 8; h++) {
                acc2[h] = add2(acc2[h], rp[h]);
                xr[h] = rp[h];
            }
        }
        __syncthreads();
        if (o < 128 || n >= 128) {
            int j = (n - o) & 255;
            const ulonglong2* xr = (const ulonglong2*)&xch[j*VPAD];
            ulonglong2 a0 = xr[0], a1 = xr[1], a2 = xr[2], a3 = xr[3];
            acc2[0] = add2(acc2[0], a0.x); acc2[1] = add2(acc2[1], a0.y);
            acc2[2] = add2(acc2[2], a1.x); acc2[3] = add2(acc2[3], a1.y);
            acc2[4] = add2(acc2[4], a2.x); acc2[5] = add2(acc2[5], a2.y);
            acc2[6] = add2(acc2[6], a3.x); acc2[7] = add2(acc2[7], a3.y);
        }
    }

    float* gx = c ? g_x1 : g_x0;
    ulonglong2* xo = (ulonglong2*)(gx + (size_t)(b*NN + n)*HP);
    xo[0] = make_ulonglong2(acc2[0], acc2[1]);
    xo[1] = make_ulonglong2(acc2[2], acc2[3]);
    xo[2] = make_ulonglong2(acc2[4], acc2[5]);
    xo[3] = make_ulonglong2(acc2[6], acc2[7]);
}

// ---------------------------------------------------------------------------
// K3: gather (CSR, atomic-free) + GIN MLP, 2 CTAs per graph, packed f32x2.
// ---------------------------------------------------------------------------
__global__ void __launch_bounds__(128) kernelD(
        const float* __restrict__ Wg1, const float* __restrict__ bg1,
        const float* __restrict__ Wg2, const float* __restrict__ bg2,
        const float* __restrict__ eps, float* __restrict__ out)
{
    __shared__ __align__(16) float xs[NN*VPAD];     // 20480 B
    __shared__ __align__(16) float Wg1s[HP*HG];     //  4096 B
    __shared__ __align__(16) float Wg2s[HG*DPE];    //  4096 B
    __shared__ __align__(16) float bg1s[HG];
    __shared__ __align__(16) float bg2s[DPE];

    int b = blockIdx.x >> 1;
    int c = blockIdx.x & 1;
    int t = threadIdx.x;     // 0..127

    // Stage x = x0 + x1 (full graph tile) + weights
    const float4* x0 = (const float4*)(g_x0 + (size_t)b*NN*HP);
    const float4* x1 = (const float4*)(g_x1 + (size_t)b*NN*HP);
    for (int i = t; i < NN*HP/4; i += 128) {
        float4 a = x0[i], bb = x1[i];
        a.x += bb.x; a.y += bb.y; a.z += bb.z; a.w += bb.w;
        *(float4*)&xs[(i >> 2)*VPAD + ((i & 3) << 2)] = a;
    }
    for (int i = t; i < HP*HG;  i += 128) Wg1s[i] = Wg1[i];
    for (int i = t; i < HG*DPE; i += 128) Wg2s[i] = Wg2[i];
    if (t < HG)  bg1s[t] = bg1[t];
    if (t < DPE) bg2s[t] = bg2[t];
    __syncthreads();

    int node = c*128 + t;
    int s0 = g_start[b*(NN+1) + node];
    int s1 = g_start[b*(NN+1) + node + 1];

    u64 agg2[8];
    #pragma unroll
    for (int h = 0; h < 8; h++) agg2[h] = 0ull;
    const int* srt = g_srt + (size_t)b*EPG;
    for (int idx = s0; idx < s1; idx++) {
        int s = srt[idx];
        const ulonglong2* xr = (const ulonglong2*)&xs[s*VPAD];
        ulonglong2 a0 = xr[0], a1 = xr[1], a2 = xr[2], a3 = xr[3];
        agg2[0] = add2(agg2[0], a0.x); agg2[1] = add2(agg2[1], a0.y);
        agg2[2] = add2(agg2[2], a1.x); agg2[3] = add2(agg2[3], a1.y);
        agg2[4] = add2(agg2[4], a2.x); agg2[5] = add2(agg2[5], a2.y);
        agg2[6] = add2(agg2[6], a3.x); agg2[7] = add2(agg2[7], a3.y);
    }

    // y = (1+eps)*x + agg
    float ge = 1.f + eps[0];
    u64 ge2 = pk2(ge, ge);
    const ulonglong2* xself = (const ulonglong2*)&xs[node*VPAD];
    u64 y2[8];
    {
        ulonglong2 a0 = xself[0], a1 = xself[1], a2 = xself[2], a3 = xself[3];
        y2[0] = fma2(ge2, a0.x, agg2[0]); y2[1] = fma2(ge2, a0.y, agg2[1]);
        y2[2] = fma2(ge2, a1.x, agg2[2]); y2[3] = fma2(ge2, a1.y, agg2[3]);
        y2[4] = fma2(ge2, a2.x, agg2[4]); y2[5] = fma2(ge2, a2.y, agg2[5]);
        y2[6] = fma2(ge2, a3.x, agg2[6]); y2[7] = fma2(ge2, a3.y, agg2[7]);
    }

    // layer 1: tg[64] = y[16] @ Wg1 + bg1 (packed over output pairs)
    u64 tg2[HG/2];
    {
        const u64* bu = (const u64*)bg1s;
        #pragma unroll
        for (int j = 0; j < HG/2; j++) tg2[j] = bu[j];
    }
    #pragma unroll
    for (int hq = 0; hq < 8; hq++) {
        float ylo, yhi; upk2(y2[hq], ylo, yhi);
        u64 ya = pk2(ylo, ylo), yb = pk2(yhi, yhi);
        const u64* wa = (const u64*)&Wg1s[(2*hq)*HG];
        const u64* wb = (const u64*)&Wg1s[(2*hq+1)*HG];
        #pragma unroll
        for (int j = 0; j < HG/2; j++) {
            tg2[j] = fma2(ya, wa[j], tg2[j]);
            tg2[j] = fma2(yb, wb[j], tg2[j]);
        }
    }

    // relu + layer 2: out[16] = relu(tg) @ Wg2 + bg2
    u64 o2[DPE/2];
    {
        const u64* bu = (const u64*)bg2s;
        #pragma unroll
        for (int d = 0; d < DPE/2; d++) o2[d] = bu[d];
    }
    #pragma unroll
    for (int j = 0; j < HG/2; j++) {
        float t0, t1; upk2(tg2[j], t0, t1);
        t0 = fmaxf(t0, 0.f); t1 = fmaxf(t1, 0.f);
        u64 ta = pk2(t0, t0), tb = pk2(t1, t1);
        const u64* wa = (const u64*)&Wg2s[(2*j)*DPE];
        const u64* wb = (const u64*)&Wg2s[(2*j+1)*DPE];
        #pragma unroll
        for (int d = 0; d < DPE/2; d++) {
            o2[d] = fma2(ta, wa[d], o2[d]);
            o2[d] = fma2(tb, wb[d], o2[d]);
        }
    }

    ulonglong2* op = (ulonglong2*)(out + (size_t)(b*NN + node)*DPE);
    op[0] = make_ulonglong2(o2[0], o2[1]);
    op[1] = make_ulonglong2(o2[2], o2[3]);
    op[2] = make_ulonglong2(o2[4], o2[5]);
    op[3] = make_ulonglong2(o2[6], o2[7]);
}

// ---------------------------------------------------------------------------
extern "C" void kernel_launch(void* const* d_in, const int* in_sizes, int n_in,
                              void* d_out, int out_size)
{
    const float* Lambda = (const float*)d_in[0];
    const float* V      = (const float*)d_in[1];
    const float* pW1    = (const float*)d_in[2];
    const float* pb1    = (const float*)d_in[3];
    const float* pW2    = (const float*)d_in[4];
    const float* pb2    = (const float*)d_in[5];
    const float* Wp1    = (const float*)d_in[6];
    const float* bp1    = (const float*)d_in[7];
    const float* Wg1    = (const float*)d_in[8];
    const float* bg1    = (const float*)d_in[9];
    const float* Wg2    = (const float*)d_in[10];
    const float* bg2    = (const float*)d_in[11];
    const float* eps    = (const float*)d_in[12];
    const int*   edge_index = (const int*)d_in[13];
    const int*   batch  = (const int*)d_in[14];
    float* out = (float*)d_out;

    const int smemB = (3*NN*VPAD + 64 + 64 + 16) * (int)sizeof(float);  // 62016 B
    static int attr_set = 0;
    cudaFuncSetAttribute(kernelB, cudaFuncAttributeMaxDynamicSharedMemorySize, smemB);
    (void)attr_set;

    kernelCSR<<<NB, 256>>>(edge_index);
    kernelB<<<NB*2, 256, smemB>>>(V, Lambda, pW1, pb1, pW2, pb2, Wp1, bp1, batch);
    kernelD<<<NB*2, 128>>>(Wg1, bg1, Wg2, bg2, eps, out);
}

// round 4
// speedup vs baseline: 1.0530x; 1.0530x over previous
#include <cuda_runtime.h>

// Problem constants (fixed by the dataset)
#define NB    128          // graphs (B)
#define NN    256          // nodes per graph
#define DPE   16           // D_pe / eigen dim
#define MM    4            // M psi copies
#define HPSI  32
#define HP    16
#define HG    64
#define NSUM  (NB*NN)      // 32768
#define EDGES (NSUM*16)    // 524288
#define EPG   (EDGES/NB)   // 4096 edges per graph (graph-contiguous)
#define VPAD  20           // padded row stride (floats) -> conflict-free LDS.128

typedef unsigned long long u64;

// Scratch (device globals: no allocation allowed)
__device__ float g_x[NSUM*HP];           // pooled features
__device__ int   g_srt[EDGES];           // CSR: src sorted by dst (per graph)
__device__ int   g_start[NB*(NN+1)];     // CSR row starts (stride 257)

// ---------------- packed f32x2 helpers ----------------
__device__ __forceinline__ u64 pk2(float lo, float hi) {
    u64 r; asm("mov.b64 %0,{%1,%2};" : "=l"(r) : "f"(lo), "f"(hi)); return r;
}
__device__ __forceinline__ void upk2(u64 v, float& lo, float& hi) {
    asm("mov.b64 {%0,%1},%2;" : "=f"(lo), "=f"(hi) : "l"(v));
}
__device__ __forceinline__ u64 fma2(u64 a, u64 b, u64 c) {
    u64 d; asm("fma.rn.f32x2 %0,%1,%2,%3;" : "=l"(d) : "l"(a), "l"(b), "l"(c)); return d;
}
__device__ __forceinline__ u64 mul2(u64 a, u64 b) {
    u64 d; asm("mul.rn.f32x2 %0,%1,%2;" : "=l"(d) : "l"(a), "l"(b)); return d;
}
__device__ __forceinline__ u64 add2(u64 a, u64 b) {
    u64 d; asm("add.rn.f32x2 %0,%1,%2;" : "=l"(d) : "l"(a), "l"(b)); return d;
}

// ---------------------------------------------------------------------------
// CSR build for graph b (runs in blocks NB..2*NB-1 of the fused kernel).
// Shared memory is carved from the dynamic buffer.
// ---------------------------------------------------------------------------
__device__ void csr_build(int b, int t, int* ism)
{
    int* cnt  = ism;            // 256
    int* cur  = ism + NN;       // 256
    int* wsum = ism + 2*NN;     // 8
    int* dstc = ism + 2*NN + 8; // 4096 cached dst

    int base = b*NN;
    cnt[t] = 0;
    __syncthreads();

    // note: g_ei_src/dst set up by caller via globals below
    extern __shared__ float smx[];   (void)smx;
    // pointers passed through constant params instead (see kernelB)
    (void)base; (void)cur; (void)wsum; (void)dstc;
}

// ---------------------------------------------------------------------------
// Fused kernel: blocks [0,NB) = pairwise phase; blocks [NB,2NB) = CSR build.
// ---------------------------------------------------------------------------
#define COMPUTE_R2(kk) do {                                                     \
    const ulonglong2* vr_ = (const ulonglong2*)&Vs[(kk)*VPAD];                  \
    ulonglong2 a_ = vr_[0], b_ = vr_[1], c_ = vr_[2], d_ = vr_[3];              \
    u64 vk_[8] = {a_.x, a_.y, b_.x, b_.y, c_.x, c_.y, d_.x, d_.y};              \
    u64 wm_[4];                                                                 \
    _Pragma("unroll")                                                           \
    for (int m_ = 0; m_ < 4; m_++) {                                            \
        u64 s_ = mul2(An2[m_][0], vk_[0]);                                      \
        _Pragma("unroll")                                                       \
        for (int j_ = 1; j_ < 8; j_++) s_ = fma2(An2[m_][j_], vk_[j_], s_);     \
        float lo_, hi_; upk2(s_, lo_, hi_);                                     \
        float w_ = lo_ + hi_;                                                   \
        wm_[m_] = pk2(w_, w_);                                                  \
    }                                                                           \
    _Pragma("unroll")                                                           \
    for (int hp_ = 0; hp_ < 8; hp_++) {                                         \
        u64 p_ = fma2(wm_[0], wp2[0][hp_], bps2[hp_]);                          \
        p_ = fma2(wm_[1], wp2[1][hp_], p_);                                     \
        p_ = fma2(wm_[2], wp2[2][hp_], p_);                                     \
        p_ = fma2(wm_[3], wp2[3][hp_], p_);                                     \
        float lo_, hi_; upk2(p_, lo_, hi_);                                     \
        lo_ = fmaxf(lo_, 0.f); hi_ = fmaxf(hi_, 0.f);                           \
        rp[hp_] = pk2(lo_, hi_);                                                \
    }                                                                           \
} while (0)

__global__ void __launch_bounds__(256) kernelB(
        const float* __restrict__ V,
        const float* __restrict__ Lambda,
        const float* __restrict__ pW1, const float* __restrict__ pb1,
        const float* __restrict__ pW2, const float* __restrict__ pb2,
        const float* __restrict__ Wp1, const float* __restrict__ bp1,
        const int*   __restrict__ batch,
        const int*   __restrict__ edge_index)
{
    extern __shared__ float sm[];
    int n = threadIdx.x;

    // ======================= CSR blocks =======================
    if (blockIdx.x >= NB) {
        int b = blockIdx.x - NB;
        int t = n;
        int* ism  = (int*)sm;
        int* cnt  = ism;             // 256
        int* cur  = ism + NN;        // 256
        int* wsum = ism + 2*NN;      // 8
        int* dstc = ism + 2*NN + 8;  // 4096

        int base = b*NN;
        cnt[t] = 0;
        __syncthreads();

        const int* srcp = edge_index + (size_t)b*EPG;
        const int* dstp = edge_index + (size_t)EDGES + (size_t)b*EPG;

        #pragma unroll
        for (int e = t; e < EPG; e += 256) {
            int d = dstp[e] - base;
            dstc[e] = d;
            atomicAdd(&cnt[d], 1);
        }
        __syncthreads();

        int v = cnt[t];
        int incl = v;
        #pragma unroll
        for (int off = 1; off < 32; off <<= 1) {
            int x = __shfl_up_sync(0xffffffffu, incl, off);
            if ((t & 31) >= off) incl += x;
        }
        if ((t & 31) == 31) wsum[t >> 5] = incl;
        __syncthreads();
        if (t == 0) {
            int s = 0;
            #pragma unroll
            for (int i = 0; i < 8; i++) { int x = wsum[i]; wsum[i] = s; s += x; }
        }
        __syncthreads();
        int excl = incl - v + wsum[t >> 5];
        g_start[b*(NN+1) + t] = excl;
        if (t == 0) g_start[b*(NN+1) + NN] = EPG;
        cur[t] = excl;
        __syncthreads();

        #pragma unroll
        for (int e = t; e < EPG; e += 256) {
            int pos = atomicAdd(&cur[dstc[e]], 1);
            g_srt[(size_t)b*EPG + pos] = srcp[e] - base;
        }
        return;
    }

    // ======================= pairwise blocks =======================
    float* Vs   = sm;                    // 5120 floats
    float* xch0 = sm + NN*VPAD;          // 5120
    float* xch1 = sm + 2*NN*VPAD;        // 5120
    float* zs   = sm + 3*NN*VPAD;        // 64
    __shared__ int bnds[2];

    int b = blockIdx.x;

    // Load V tile [256 x 16] into padded smem
    const float4* vg = (const float4*)(V + (size_t)b*NN*DPE);
    for (int i = n; i < NN*DPE/4; i += 256) {
        float4 v = vg[i];
        *(float4*)&Vs[(i >> 2)*VPAD + ((i & 3) << 2)] = v;
    }

    // psi MLP (threads 0..63), eigen-count via binary search (threads 0,1)
    float pacc = 0.f;
    if (n < DPE*MM) {
        int d = n >> 2, m = n & 3;
        float lam = Lambda[b*DPE + d];
        pacc = pb2[m];
        #pragma unroll
        for (int h = 0; h < HPSI; h++) {
            float v = fmaf(lam, pW1[m*HPSI + h], pb1[m*HPSI + h]);
            pacc = fmaf(fmaxf(v, 0.f), pW2[m*HPSI + h], pacc);
        }
    }
    if (n < 2) {
        int key = b + n;            // first index with batch[i] >= key
        int lo = 0, hi = NSUM;
        while (lo < hi) {
            int mid = (lo + hi) >> 1;
            if (batch[mid] < key) lo = mid + 1; else hi = mid;
        }
        bnds[n] = lo;
    }

    // Projection weights, packed, in registers
    u64 wp2[MM][HP/2];
    u64 bps2[HP/2];
    #pragma unroll
    for (int m = 0; m < MM; m++)
        #pragma unroll
        for (int hp = 0; hp < HP/2; hp++)
            wp2[m][hp] = pk2(Wp1[m*HP + 2*hp], Wp1[m*HP + 2*hp + 1]);
    #pragma unroll
    for (int hp = 0; hp < HP/2; hp++) bps2[hp] = pk2(bp1[2*hp], bp1[2*hp+1]);

    __syncthreads();
    if (n < DPE*MM) {
        int cnt = bnds[1] - bnds[0];
        zs[n] = ((n >> 2) < cnt) ? pacc : 0.f;
    }
    __syncthreads();

    // Per-thread packed scaled row: An2[m][j] = (V[n,2j]Z[2j,m], V[n,2j+1]Z[2j+1,m])
    u64 An2[MM][DPE/2];
    {
        const float4* vrow = (const float4*)&Vs[n*VPAD];
        #pragma unroll
        for (int q = 0; q < 4; q++) {
            float4 vv = vrow[q];
            #pragma unroll
            for (int m = 0; m < MM; m++) {
                An2[m][2*q]   = pk2(vv.x * zs[(4*q)*MM + m],   vv.y * zs[(4*q+1)*MM + m]);
                An2[m][2*q+1] = pk2(vv.z * zs[(4*q+2)*MM + m], vv.w * zs[(4*q+3)*MM + m]);
            }
        }
    }

    u64 acc2[HP/2];
    #pragma unroll
    for (int h = 0; h < HP/2; h++) acc2[h] = 0ull;

    u64 rp[8];

    // o = 0: diagonal pair (n,n) counted once
    {
        COMPUTE_R2(n);
        #pragma unroll
        for (int h = 0; h < 8; h++) acc2[h] = add2(acc2[h], rp[h]);
    }

    // o = 1..128: each unordered pair computed exactly once
    for (int o = 1; o <= 128; o++) {
        int  k   = (n + o) & 255;
        bool act = (o < 128) || (n < 128);   // o=128: only lower half computes
        float* xch = (o & 1) ? xch1 : xch0;
        if (act) {
            COMPUTE_R2(k);
            u64* xr = (u64*)&xch[n*VPAD];
            #pragma unroll
            for (int h = 0; h < 8; h++) {
                acc2[h] = add2(acc2[h], rp[h]);
                xr[h] = rp[h];
            }
        }
        __syncthreads();
        if (o < 128 || n >= 128) {
            int j = (n - o) & 255;
            const ulonglong2* xr = (const ulonglong2*)&xch[j*VPAD];
            ulonglong2 a0 = xr[0], a1 = xr[1], a2 = xr[2], a3 = xr[3];
            acc2[0] = add2(acc2[0], a0.x); acc2[1] = add2(acc2[1], a0.y);
            acc2[2] = add2(acc2[2], a1.x); acc2[3] = add2(acc2[3], a1.y);
            acc2[4] = add2(acc2[4], a2.x); acc2[5] = add2(acc2[5], a2.y);
            acc2[6] = add2(acc2[6], a3.x); acc2[7] = add2(acc2[7], a3.y);
        }
    }

    ulonglong2* xo = (ulonglong2*)(g_x + (size_t)(b*NN + n)*HP);
    xo[0] = make_ulonglong2(acc2[0], acc2[1]);
    xo[1] = make_ulonglong2(acc2[2], acc2[3]);
    xo[2] = make_ulonglong2(acc2[4], acc2[5]);
    xo[3] = make_ulonglong2(acc2[6], acc2[7]);
}

// ---------------------------------------------------------------------------
// Kernel D: gather (CSR, atomic-free) + GIN MLP, 2 CTAs per graph, f32x2.
// ---------------------------------------------------------------------------
__global__ void __launch_bounds__(128) kernelD(
        const float* __restrict__ Wg1, const float* __restrict__ bg1,
        const float* __restrict__ Wg2, const float* __restrict__ bg2,
        const float* __restrict__ eps, float* __restrict__ out)
{
    __shared__ __align__(16) float xs[NN*VPAD];     // 20480 B
    __shared__ __align__(16) float Wg1s[HP*HG];     //  4096 B
    __shared__ __align__(16) float Wg2s[HG*DPE];    //  4096 B
    __shared__ __align__(16) float bg1s[HG];
    __shared__ __align__(16) float bg2s[DPE];

    int b = blockIdx.x >> 1;
    int c = blockIdx.x & 1;
    int t = threadIdx.x;     // 0..127

    // Stage x tile + weights
    const float4* xg = (const float4*)(g_x + (size_t)b*NN*HP);
    for (int i = t; i < NN*HP/4; i += 128) {
        float4 a = xg[i];
        *(float4*)&xs[(i >> 2)*VPAD + ((i & 3) << 2)] = a;
    }
    for (int i = t; i < HP*HG;  i += 128) Wg1s[i] = Wg1[i];
    for (int i = t; i < HG*DPE; i += 128) Wg2s[i] = Wg2[i];
    if (t < HG)  bg1s[t] = bg1[t];
    if (t < DPE) bg2s[t] = bg2[t];
    __syncthreads();

    int node = c*128 + t;
    int s0 = g_start[b*(NN+1) + node];
    int s1 = g_start[b*(NN+1) + node + 1];

    u64 agg2[8];
    #pragma unroll
    for (int h = 0; h < 8; h++) agg2[h] = 0ull;
    const int* srt = g_srt + (size_t)b*EPG;
    for (int idx = s0; idx < s1; idx++) {
        int s = srt[idx];
        const ulonglong2* xr = (const ulonglong2*)&xs[s*VPAD];
        ulonglong2 a0 = xr[0], a1 = xr[1], a2 = xr[2], a3 = xr[3];
        agg2[0] = add2(agg2[0], a0.x); agg2[1] = add2(agg2[1], a0.y);
        agg2[2] = add2(agg2[2], a1.x); agg2[3] = add2(agg2[3], a1.y);
        agg2[4] = add2(agg2[4], a2.x); agg2[5] = add2(agg2[5], a2.y);
        agg2[6] = add2(agg2[6], a3.x); agg2[7] = add2(agg2[7], a3.y);
    }

    // y = (1+eps)*x + agg
    float ge = 1.f + eps[0];
    u64 ge2 = pk2(ge, ge);
    const ulonglong2* xself = (const ulonglong2*)&xs[node*VPAD];
    u64 y2[8];
    {
        ulonglong2 a0 = xself[0], a1 = xself[1], a2 = xself[2], a3 = xself[3];
        y2[0] = fma2(ge2, a0.x, agg2[0]); y2[1] = fma2(ge2, a0.y, agg2[1]);
        y2[2] = fma2(ge2, a1.x, agg2[2]); y2[3] = fma2(ge2, a1.y, agg2[3]);
        y2[4] = fma2(ge2, a2.x, agg2[4]); y2[5] = fma2(ge2, a2.y, agg2[5]);
        y2[6] = fma2(ge2, a3.x, agg2[6]); y2[7] = fma2(ge2, a3.y, agg2[7]);
    }

    // layer 1: tg[64] = y[16] @ Wg1 + bg1 (packed over output pairs)
    u64 tg2[HG/2];
    {
        const u64* bu = (const u64*)bg1s;
        #pragma unroll
        for (int j = 0; j < HG/2; j++) tg2[j] = bu[j];
    }
    #pragma unroll
    for (int hq = 0; hq < 8; hq++) {
        float ylo, yhi; upk2(y2[hq], ylo, yhi);
        u64 ya = pk2(ylo, ylo), yb = pk2(yhi, yhi);
        const u64* wa = (const u64*)&Wg1s[(2*hq)*HG];
        const u64* wb = (const u64*)&Wg1s[(2*hq+1)*HG];
        #pragma unroll
        for (int j = 0; j < HG/2; j++) {
            tg2[j] = fma2(ya, wa[j], tg2[j]);
            tg2[j] = fma2(yb, wb[j], tg2[j]);
        }
    }

    // relu + layer 2: out[16] = relu(tg) @ Wg2 + bg2
    u64 o2[DPE/2];
    {
        const u64* bu = (const u64*)bg2s;
        #pragma unroll
        for (int d = 0; d < DPE/2; d++) o2[d] = bu[d];
    }
    #pragma unroll
    for (int j = 0; j < HG/2; j++) {
        float t0, t1; upk2(tg2[j], t0, t1);
        t0 = fmaxf(t0, 0.f); t1 = fmaxf(t1, 0.f);
        u64 ta = pk2(t0, t0), tb = pk2(t1, t1);
        const u64* wa = (const u64*)&Wg2s[(2*j)*DPE];
        const u64* wb = (const u64*)&Wg2s[(2*j+1)*DPE];
        #pragma unroll
        for (int d = 0; d < DPE/2; d++) {
            o2[d] = fma2(ta, wa[d], o2[d]);
            o2[d] = fma2(tb, wb[d], o2[d]);
        }
    }

    ulonglong2* op = (ulonglong2*)(out + (size_t)(b*NN + node)*DPE);
    op[0] = make_ulonglong2(o2[0], o2[1]);
    op[1] = make_ulonglong2(o2[2], o2[3]);
    op[2] = make_ulonglong2(o2[4], o2[5]);
    op[3] = make_ulonglong2(o2[6], o2[7]);
}

// ---------------------------------------------------------------------------
extern "C" void kernel_launch(void* const* d_in, const int* in_sizes, int n_in,
                              void* d_out, int out_size)
{
    const float* Lambda = (const float*)d_in[0];
    const float* V      = (const float*)d_in[1];
    const float* pW1    = (const float*)d_in[2];
    const float* pb1    = (const float*)d_in[3];
    const float* pW2    = (const float*)d_in[4];
    const float* pb2    = (const float*)d_in[5];
    const float* Wp1    = (const float*)d_in[6];
    const float* bp1    = (const float*)d_in[7];
    const float* Wg1    = (const float*)d_in[8];
    const float* bg1    = (const float*)d_in[9];
    const float* Wg2    = (const float*)d_in[10];
    const float* bg2    = (const float*)d_in[11];
    const float* eps    = (const float*)d_in[12];
    const int*   edge_index = (const int*)d_in[13];
    const int*   batch  = (const int*)d_in[14];
    float* out = (float*)d_out;

    const int smemB = (3*NN*VPAD + 64) * (int)sizeof(float);   // 61696 B
    cudaFuncSetAttribute(kernelB, cudaFuncAttributeMaxDynamicSharedMemorySize, smemB);

    kernelB<<<NB*2, 256, smemB>>>(V, Lambda, pW1, pb1, pW2, pb2, Wp1, bp1,
                                  batch, edge_index);
    kernelD<<<NB*2, 128>>>(Wg1, bg1, Wg2, bg2, eps, out);
}